// round 11
// baseline (speedup 1.0000x reference)
#include <cuda_runtime.h>
#include <cstdint>

// x: [B, 64,64,64] f32,  z: [B, P, 3] f32;  B=64, P=4096
// out = concat( suffix-cumsum(hist) [B*G f32],  x * (suffix>0) [B*G f32] )
//
// SINGLE fused kernel. Block = (batch b, ix-slab of 8). Each block re-reads
// its batch's 4096 points (48 KB; shared via L2 among the batch's 8 blocks),
// bins matching points into a 32 KB SMEM u8 histogram, then streams its
// 32768 output elements: SMEM word -> 16-lane shfl suffix scan -> x ->
// counts + rmask. No global histogram, no reset, no second launch, and every
// global address is a pure function of (block, thread).

#define NB     64
#define NP     4096
#define NG     (64 * 64 * 64)
#define NTOT   (NB * NG)
#define SLABS  8                   // ix-slabs per batch
#define SLABW  (64 / SLABS)        // 8 ix values per slab
#define SLAB_BINS (SLABW * 64 * 64)        // 32768 bins per block
#define SLAB_W    (SLAB_BINS / 4)          // 8192 u32 words (32 KB)
#define THREADS 256

__global__ void __launch_bounds__(THREADS)
k_fused(const float* __restrict__ z,
        const float4* __restrict__ x,
        float4* __restrict__ counts,
        float4* __restrict__ rmask) {
    __shared__ unsigned int hist[SLAB_W];          // 32 KB: u8 bins, 4/word

    int blk  = blockIdx.x;                         // 0 .. NB*SLABS-1
    int b    = blk >> 3;                           // batch
    int slab = blk & 7;                            // ix-slab
    int tid  = threadIdx.x;

    // Phase 1: zero SMEM hist (32 words per thread).
    #pragma unroll
    for (int k = 0; k < SLAB_W / THREADS; k++)
        hist[tid + k * THREADS] = 0u;
    __syncthreads();

    // Phase 2: scan this batch's points; bin those in our ix slab.
    const float* zb = z + (size_t)b * NP * 3;
    #pragma unroll
    for (int k = 0; k < NP / THREADS; k++) {
        int p = tid + k * THREADS;
        float zx = zb[3 * p + 0];
        float zy = zb[3 * p + 1];
        float zz = zb[3 * p + 2];
        int ix = (int)(zx * 64.0f); ix = ix < 0 ? 0 : (ix > 63 ? 63 : ix);
        int iy = (int)(zy * 64.0f); iy = iy < 0 ? 0 : (iy > 63 ? 63 : iy);
        int iz = (int)(zz * 64.0f); iz = iz < 0 ? 0 : (iz > 63 ? 63 : iz);
        if ((ix >> 3) == slab) {
            unsigned int bin = (unsigned int)(ix & 7) * 4096u
                             + (unsigned int)iy * 64u + (unsigned int)iz;
            atomicAdd(&hist[bin >> 2], 1u << (8u * (bin & 3u)));
        }
    }
    __syncthreads();

    // Phase 3: stream outputs. Block covers float4 chunks
    // [g4_base, g4_base + SLAB_W); chunk c's 4 bins are SMEM word c.
    int g4_base = b * (NG / 4) + slab * (SLAB_W);  // slab*8192
    #pragma unroll 4
    for (int k = 0; k < SLAB_W / THREADS; k++) {
        int c  = tid + k * THREADS;                // 0 .. 8191
        int g4 = g4_base + c;
        int lane16 = c & 15;                       // position within 64-row

        unsigned int hw = hist[c];
        float c0 = (float)( hw        & 0xffu);
        float c1 = (float)((hw >> 8)  & 0xffu);
        float c2 = (float)((hw >> 16) & 0xffu);
        float c3 = (float)((hw >> 24) & 0xffu);

        // 16-lane suffix scan of per-word sums (warp = 2 aligned rows).
        float v = c0 + c1 + c2 + c3;
        #pragma unroll
        for (int off = 1; off < 16; off <<= 1) {
            float t = __shfl_down_sync(0xffffffffu, v, off, 16);
            if (lane16 + off < 16) v += t;
        }
        float o0 = v;
        float o1 = o0 - c0;
        float o2 = o1 - c1;
        float o3 = o2 - c2;

        float4 xr = x[g4];                         // independent address
        __stcs(&counts[g4], make_float4(o0, o1, o2, o3));
        __stcs(&rmask[g4],  make_float4(o0 > 0.f ? xr.x : 0.f,
                                        o1 > 0.f ? xr.y : 0.f,
                                        o2 > 0.f ? xr.z : 0.f,
                                        o3 > 0.f ? xr.w : 0.f));
    }
}

// ---------------------------------------------------------------------------
extern "C" void kernel_launch(void* const* d_in, const int* in_sizes, int n_in,
                              void* d_out, int out_size) {
    const float* x = (const float*)d_in[0];
    const float* z = (const float*)d_in[1];

    float* counts = (float*)d_out;
    float* rmask  = (float*)d_out + (size_t)NTOT;

    k_fused<<<NB * SLABS, THREADS>>>(z, (const float4*)x,
                                     (float4*)counts, (float4*)rmask);
}

// round 12
// speedup vs baseline: 1.0471x; 1.0471x over previous
#include <cuda_runtime.h>
#include <cstdint>

// x: [B, 64,64,64] f32,  z: [B, P, 3] f32;  B=64, P=4096
// out = concat( suffix-cumsum(hist) [B*G f32],  x * (suffix>0) [B*G f32] )
//
// K1: per-point 18-bit bin code -> g_code (1 MB, overwritten each replay).
// K2: block = (batch, 4-ix slab). 16 KB SMEM u8 histogram; scan the batch's
//     4096 codes (16 KB, L2-hot), bin matches, then stream 16384 outputs:
//     SMEM word -> 16-lane shfl suffix scan -> predicated x -> stores.
//     x predicate derives from SMEM (no global dependent chain).

#define NB     64
#define NP     4096
#define NG     (64 * 64 * 64)
#define NTOT   (NB * NG)
#define SLABS  16                          // 4 ix values per slab
#define SLAB_BINS (4 * 64 * 64)            // 16384 bins per block
#define SLAB_W    (SLAB_BINS / 4)          // 4096 u32 words (16 KB)
#define THREADS 256

__device__ unsigned int g_code[NB * NP];   // 1 MB

// ---------------------------------------------------------------------------
// K1: compute linear bin code per point. 1 thread/point, fully coalesced.
// ---------------------------------------------------------------------------
__global__ void k_code(const float* __restrict__ z) {
    int t = blockIdx.x * blockDim.x + threadIdx.x;
    if (t >= NB * NP) return;
    float zx = z[3 * t + 0];
    float zy = z[3 * t + 1];
    float zz = z[3 * t + 2];
    int ix = (int)(zx * 64.0f); ix = ix < 0 ? 0 : (ix > 63 ? 63 : ix);
    int iy = (int)(zy * 64.0f); iy = iy < 0 ? 0 : (iy > 63 ? 63 : iy);
    int iz = (int)(zz * 64.0f); iz = iz < 0 ? 0 : (iz > 63 ? 63 : iz);
    g_code[t] = (unsigned int)(ix * 4096 + iy * 64 + iz);
}

// ---------------------------------------------------------------------------
// K2: fused SMEM histogram + suffix scan + masked output.
// ---------------------------------------------------------------------------
__global__ void __launch_bounds__(THREADS)
k_fused(const float4* __restrict__ x,
        float4* __restrict__ counts,
        float4* __restrict__ rmask) {
    __shared__ unsigned int hist[SLAB_W];          // 16 KB: u8 bins, 4/word

    int blk  = blockIdx.x;                         // 0 .. NB*SLABS-1
    int b    = blk >> 4;                           // batch
    int slab = blk & 15;                           // 4-ix slab
    int tid  = threadIdx.x;

    // Phase 1: zero SMEM hist (16 words per thread).
    #pragma unroll
    for (int k = 0; k < SLAB_W / THREADS; k++)
        hist[tid + k * THREADS] = 0u;
    __syncthreads();

    // Phase 2: scan this batch's 4096 codes; bin those in our slab.
    const unsigned int* cb = g_code + b * NP;
    #pragma unroll
    for (int k = 0; k < NP / THREADS; k++) {
        unsigned int code = cb[tid + k * THREADS];
        if ((int)(code >> 14) == slab) {           // avg 1 match per thread
            unsigned int bin = code & 16383u;
            atomicAdd(&hist[bin >> 2], 1u << (8u * (bin & 3u)));
        }
    }
    __syncthreads();

    // Phase 3: stream outputs. Block covers float4 chunks
    // [g4_base, g4_base + SLAB_W); chunk c's 4 bins are SMEM word c.
    int g4_base = b * (NG / 4) + slab * SLAB_W;
    #pragma unroll 4
    for (int k = 0; k < SLAB_W / THREADS; k++) {
        int c  = tid + k * THREADS;                // 0 .. 4095
        int g4 = g4_base + c;
        int lane16 = c & 15;                       // position within 64-row

        unsigned int hw = hist[c];
        float c0 = (float)( hw        & 0xffu);
        float c1 = (float)((hw >> 8)  & 0xffu);
        float c2 = (float)((hw >> 16) & 0xffu);
        float c3 = (float)((hw >> 24) & 0xffu);

        // 16-lane suffix scan of per-word sums (warp = 2 aligned rows).
        float v = c0 + c1 + c2 + c3;
        #pragma unroll
        for (int off = 1; off < 16; off <<= 1) {
            float t = __shfl_down_sync(0xffffffffu, v, off, 16);
            if (lane16 + off < 16) v += t;
        }
        float o0 = v;
        float o1 = o0 - c0;
        float o2 = o1 - c1;
        float o3 = o2 - c2;

        __stcs(&counts[g4], make_float4(o0, o1, o2, o3));

        // Predicated x read, branchless: masked lanes collapse onto the
        // row's first sector. Predicate is SMEM-derived -> cheap.
        int gi = (o0 > 0.f) ? g4 : (g4 & ~15);
        float4 xr = x[gi];
        __stcs(&rmask[g4], make_float4(o0 > 0.f ? xr.x : 0.f,
                                       o1 > 0.f ? xr.y : 0.f,
                                       o2 > 0.f ? xr.z : 0.f,
                                       o3 > 0.f ? xr.w : 0.f));
    }
}

// ---------------------------------------------------------------------------
extern "C" void kernel_launch(void* const* d_in, const int* in_sizes, int n_in,
                              void* d_out, int out_size) {
    const float* x = (const float*)d_in[0];
    const float* z = (const float*)d_in[1];

    float* counts = (float*)d_out;
    float* rmask  = (float*)d_out + (size_t)NTOT;

    {
        int n = NB * NP;
        k_code<<<(n + 255) / 256, 256>>>(z);
    }
    k_fused<<<NB * SLABS, THREADS>>>((const float4*)x,
                                     (float4*)counts, (float4*)rmask);
}